// round 1
// baseline (speedup 1.0000x reference)
#include <cuda_runtime.h>
#include <cuda_fp16.h>
#include <cstdint>

#define KC    64            // number of selected columns
#define DCOL  1024          // columns of x
#define NTRI  2016          // upper-triangular terms
#define NM3   512
#define NM4   512
#define NM5   512
#define TPB   64            // threads per block
#define ROWS_PER_BLOCK (TPB*2)
#define NBLOCKS 256         // 256 * 128 rows = 32768

// -------- persistent scratch (no allocations allowed) --------
__device__ float    g_tri[NTRI];     // packed triu(b,1), row-major (i asc, j asc)
__device__ uint2    g_rec3[NM3];     // x: i0|i1<<8|i2<<16, y: c bits
__device__ uint2    g_rec4[NM4];     // x: i0..i3 packed bytes, y: c bits
__device__ uint4    g_rec5[NM5];     // x: i0..i3 bytes, y: i4, z: c bits, w: pad
__device__ float    g_a[KC];
__device__ unsigned g_xoff[KC];      // S[k] (element index into a row of x)

// -------- prep kernel: pack coefficients/indices once per graph replay --------
__global__ void prep_kernel(const float* __restrict__ b,
                            const int*   __restrict__ S,
                            const float* __restrict__ a,
                            const int*   __restrict__ idx3, const float* __restrict__ c3,
                            const int*   __restrict__ idx4, const float* __restrict__ c4,
                            const int*   __restrict__ idx5, const float* __restrict__ c5)
{
    int t = blockIdx.x * blockDim.x + threadIdx.x;
    if (t < NTRI) {
        // map p -> (i, j), same static order the main kernel unrolls
        int rem = t, i = 0;
        while (rem >= 63 - i) { rem -= 63 - i; ++i; }
        int j = i + 1 + rem;
        g_tri[t] = b[i * 64 + j];
    }
    if (t < NM3) {
        unsigned p = (unsigned)idx3[t*3+0] | ((unsigned)idx3[t*3+1] << 8)
                   | ((unsigned)idx3[t*3+2] << 16);
        uint2 r; r.x = p; r.y = __float_as_uint(c3[t]);
        g_rec3[t] = r;
    }
    if (t < NM4) {
        unsigned p = (unsigned)idx4[t*4+0] | ((unsigned)idx4[t*4+1] << 8)
                   | ((unsigned)idx4[t*4+2] << 16) | ((unsigned)idx4[t*4+3] << 24);
        uint2 r; r.x = p; r.y = __float_as_uint(c4[t]);
        g_rec4[t] = r;
    }
    if (t < NM5) {
        unsigned p = (unsigned)idx5[t*5+0] | ((unsigned)idx5[t*5+1] << 8)
                   | ((unsigned)idx5[t*5+2] << 16) | ((unsigned)idx5[t*5+3] << 24);
        uint4 r; r.x = p; r.y = (unsigned)idx5[t*5+4];
        r.z = __float_as_uint(c5[t]); r.w = 0u;
        g_rec5[t] = r;
    }
    if (t < KC) {
        g_a[t]    = a[t];
        g_xoff[t] = (unsigned)S[t];
    }
}

// -------- main kernel: 2 rows per thread --------
__global__ __launch_bounds__(TPB)
void poly_kernel(const float* __restrict__ x, float* __restrict__ out)
{
    __shared__ float    s_tri[NTRI];            // 8064 B
    __shared__ uint2    s_rec3[NM3];            // 4 KB
    __shared__ uint2    s_rec4[NM4];            // 4 KB
    __shared__ uint4    s_rec5[NM5];            // 8 KB
    __shared__ float    s_a[KC];
    __shared__ unsigned s_xi[KC];
    __shared__ __half   s_x[KC][ROWS_PER_BLOCK];// [64][128] half = 16 KB, row stride 256B

    const int tid = threadIdx.x;

    // cooperative preload of coefficients into shared
    {
        const float4* ts = (const float4*)g_tri;
        float4*       td = (float4*)s_tri;
        #pragma unroll 1
        for (int i = tid; i < NTRI/4; i += TPB) td[i] = ts[i];
        #pragma unroll 1
        for (int i = tid; i < NM3; i += TPB) s_rec3[i] = g_rec3[i];
        #pragma unroll 1
        for (int i = tid; i < NM4; i += TPB) s_rec4[i] = g_rec4[i];
        #pragma unroll 1
        for (int i = tid; i < NM5; i += TPB) s_rec5[i] = g_rec5[i];
        if (tid < KC) { s_a[tid] = g_a[tid]; s_xi[tid] = g_xoff[tid]; }
    }
    __syncthreads();

    const long long rowA = ((long long)blockIdx.x * TPB + tid) * 2;

    float acc[2];
    float xv[KC];

    #pragma unroll 1
    for (int pass = 0; pass < 2; ++pass) {
        const float* xr = x + (rowA + pass) * DCOL;
        // gather the 64 selected columns of this row (scattered LDG, high MLP)
        #pragma unroll
        for (int k = 0; k < KC; ++k) xv[k] = __ldg(xr + s_xi[k]);

        // linear term (fp32 exact)
        float a0 = 0.f;
        #pragma unroll
        for (int k = 0; k < KC; ++k) a0 = fmaf(s_a[k], xv[k], a0);

        // quadratic form: fully unrolled triangular loop, x in registers,
        // packed-tri coefficients via broadcast LDS.128
        {
            const float4* tri4 = (const float4*)s_tri;
            float4 tb = make_float4(0.f, 0.f, 0.f, 0.f);
            int p = 0;
            #pragma unroll
            for (int i = 0; i < KC - 1; ++i) {
                float s = 0.f;
                #pragma unroll
                for (int j = i + 1; j < KC; ++j) {
                    if ((p & 3) == 0) tb = tri4[p >> 2];
                    float bv = ((p & 3) == 0) ? tb.x :
                               ((p & 3) == 1) ? tb.y :
                               ((p & 3) == 2) ? tb.z : tb.w;
                    s = fmaf(bv, xv[j], s);
                    ++p;
                }
                a0 = fmaf(s, xv[i], a0);
            }
        }
        acc[pass] = a0;

        // publish fp16 copy for the monomial phase (this thread's own column)
        #pragma unroll
        for (int k = 0; k < KC; ++k)
            s_x[k][2 * tid + pass] = __float2half(xv[k]);
    }

    // -------- monomials: two rows at once via half2 --------
    // thread's half2 column base: &s_x[0][2*tid]; operand byte offset = idx*256
    const char* xb = (const char*)(&s_x[0][0]) + 4 * tid;
    float m0 = 0.f, m1 = 0.f;

    #pragma unroll 4
    for (int t3 = 0; t3 < NM3; ++t3) {
        uint2 r = s_rec3[t3];
        unsigned o0 = (r.x << 8) & 0xFF00u;
        unsigned o1 =  r.x       & 0xFF00u;
        unsigned o2 = (r.x >> 8) & 0xFF00u;
        __half2 pr = __hmul2(*(const __half2*)(xb + o0),
                             *(const __half2*)(xb + o1));
        pr = __hmul2(pr, *(const __half2*)(xb + o2));
        float2 pf = __half22float2(pr);
        float c = __uint_as_float(r.y);
        m0 = fmaf(c, pf.x, m0);
        m1 = fmaf(c, pf.y, m1);
    }

    #pragma unroll 4
    for (int t4 = 0; t4 < NM4; ++t4) {
        uint2 r = s_rec4[t4];
        unsigned o0 = (r.x << 8)  & 0xFF00u;
        unsigned o1 =  r.x        & 0xFF00u;
        unsigned o2 = (r.x >> 8)  & 0xFF00u;
        unsigned o3 = (r.x >> 16) & 0xFF00u;
        __half2 p01 = __hmul2(*(const __half2*)(xb + o0),
                              *(const __half2*)(xb + o1));
        __half2 p23 = __hmul2(*(const __half2*)(xb + o2),
                              *(const __half2*)(xb + o3));
        __half2 pr  = __hmul2(p01, p23);
        float2 pf = __half22float2(pr);
        float c = __uint_as_float(r.y);
        m0 = fmaf(c, pf.x, m0);
        m1 = fmaf(c, pf.y, m1);
    }

    #pragma unroll 4
    for (int t5 = 0; t5 < NM5; ++t5) {
        uint4 r = s_rec5[t5];
        unsigned o0 = (r.x << 8)  & 0xFF00u;
        unsigned o1 =  r.x        & 0xFF00u;
        unsigned o2 = (r.x >> 8)  & 0xFF00u;
        unsigned o3 = (r.x >> 16) & 0xFF00u;
        unsigned o4 =  r.y << 8;
        __half2 p01 = __hmul2(*(const __half2*)(xb + o0),
                              *(const __half2*)(xb + o1));
        __half2 p23 = __hmul2(*(const __half2*)(xb + o2),
                              *(const __half2*)(xb + o3));
        __half2 pr  = __hmul2(__hmul2(p01, p23),
                              *(const __half2*)(xb + o4));
        float2 pf = __half22float2(pr);
        float c = __uint_as_float(r.z);
        m0 = fmaf(c, pf.x, m0);
        m1 = fmaf(c, pf.y, m1);
    }

    float2 o2v;
    o2v.x = acc[0] + m0;
    o2v.y = acc[1] + m1;
    ((float2*)out)[blockIdx.x * TPB + tid] = o2v;
}

// -------- launch --------
extern "C" void kernel_launch(void* const* d_in, const int* in_sizes, int n_in,
                              void* d_out, int out_size)
{
    const float* x    = (const float*)d_in[0];
    const int*   S    = (const int*)  d_in[1];
    const float* a    = (const float*)d_in[2];
    const float* b    = (const float*)d_in[3];
    const int*   idx3 = (const int*)  d_in[4];
    const float* c3   = (const float*)d_in[5];
    const int*   idx4 = (const int*)  d_in[6];
    const float* c4   = (const float*)d_in[7];
    const int*   idx5 = (const int*)  d_in[8];
    const float* c5   = (const float*)d_in[9];
    float* out = (float*)d_out;

    prep_kernel<<<8, 256>>>(b, S, a, idx3, c3, idx4, c4, idx5, c5);
    poly_kernel<<<NBLOCKS, TPB>>>(x, out);
}

// round 2
// speedup vs baseline: 1.5261x; 1.5261x over previous
#include <cuda_runtime.h>
#include <cuda_fp16.h>
#include <cstdint>

#define KC    64            // number of selected columns
#define DCOL  1024          // columns of x
#define NTRI  2016          // upper-triangular terms
#define NM3   512
#define NM4   512
#define NM5   512
#define TPB   128           // threads per block
#define ROWS_PER_BLOCK 128  // 1 row per thread in phase A
#define NPAIR  (ROWS_PER_BLOCK/2)   // 64 row-pairs per block
#define NBLOCKS 256         // 256 * 128 rows = 32768

// -------- persistent scratch (no allocations allowed) --------
__device__ float    g_tri[NTRI];     // packed triu(b,1), row-major (i asc, j asc)
__device__ uint2    g_rec3[NM3];     // x: i0|i1<<8|i2<<16, y: c bits
__device__ uint2    g_rec4[NM4];     // x: i0..i3 packed bytes, y: c bits
__device__ uint4    g_rec5[NM5];     // x: i0..i3 bytes, y: i4, z: c bits, w: pad
__device__ float    g_a[KC];
__device__ unsigned g_xoff[KC];      // S[k] (element index into a row of x)

// -------- prep kernel: pack coefficients/indices once per graph replay --------
__global__ void prep_kernel(const float* __restrict__ b,
                            const int*   __restrict__ S,
                            const float* __restrict__ a,
                            const int*   __restrict__ idx3, const float* __restrict__ c3,
                            const int*   __restrict__ idx4, const float* __restrict__ c4,
                            const int*   __restrict__ idx5, const float* __restrict__ c5)
{
    int t = blockIdx.x * blockDim.x + threadIdx.x;
    if (t < NTRI) {
        // map p -> (i, j), same static order the main kernel unrolls
        int rem = t, i = 0;
        while (rem >= 63 - i) { rem -= 63 - i; ++i; }
        int j = i + 1 + rem;
        g_tri[t] = b[i * 64 + j];
    }
    if (t < NM3) {
        unsigned p = (unsigned)idx3[t*3+0] | ((unsigned)idx3[t*3+1] << 8)
                   | ((unsigned)idx3[t*3+2] << 16);
        uint2 r; r.x = p; r.y = __float_as_uint(c3[t]);
        g_rec3[t] = r;
    }
    if (t < NM4) {
        unsigned p = (unsigned)idx4[t*4+0] | ((unsigned)idx4[t*4+1] << 8)
                   | ((unsigned)idx4[t*4+2] << 16) | ((unsigned)idx4[t*4+3] << 24);
        uint2 r; r.x = p; r.y = __float_as_uint(c4[t]);
        g_rec4[t] = r;
    }
    if (t < NM5) {
        unsigned p = (unsigned)idx5[t*5+0] | ((unsigned)idx5[t*5+1] << 8)
                   | ((unsigned)idx5[t*5+2] << 16) | ((unsigned)idx5[t*5+3] << 24);
        uint4 r; r.x = p; r.y = (unsigned)idx5[t*5+4];
        r.z = __float_as_uint(c5[t]); r.w = 0u;
        g_rec5[t] = r;
    }
    if (t < KC) {
        g_a[t]    = a[t];
        g_xoff[t] = (unsigned)S[t];
    }
}

// -------- main kernel: 1 row/thread quad phase, 2-way split monomial phase ----
__global__ __launch_bounds__(TPB)
void poly_kernel(const float* __restrict__ x, float* __restrict__ out)
{
    __shared__ float    s_tri[NTRI];             // 8064 B
    __shared__ uint2    s_rec3[NM3];             // 4 KB
    __shared__ uint2    s_rec4[NM4];             // 4 KB
    __shared__ uint4    s_rec5[NM5];             // 8 KB
    __shared__ float    s_a[KC];
    __shared__ unsigned s_xi[KC];
    __shared__ __half   s_x[KC][ROWS_PER_BLOCK]; // [64][128] half = 16 KB, row stride 256B
    __shared__ float    s_acc[ROWS_PER_BLOCK];   // 512 B, per-row lin+quad
    __shared__ float2   s_red[2][NPAIR];         // 1 KB, monomial partials

    const int tid = threadIdx.x;

    // cooperative preload of coefficients into shared
    {
        const float4* ts = (const float4*)g_tri;
        float4*       td = (float4*)s_tri;
        #pragma unroll 1
        for (int i = tid; i < NTRI/4; i += TPB) td[i] = ts[i];
        #pragma unroll 1
        for (int i = tid; i < NM3; i += TPB) s_rec3[i] = g_rec3[i];
        #pragma unroll 1
        for (int i = tid; i < NM4; i += TPB) s_rec4[i] = g_rec4[i];
        #pragma unroll 1
        for (int i = tid; i < NM5; i += TPB) s_rec5[i] = g_rec5[i];
        if (tid < KC) { s_a[tid] = g_a[tid]; s_xi[tid] = g_xoff[tid]; }
    }
    __syncthreads();

    // ---------------- phase A: gather + linear + quadratic (fp32, registers) --
    {
        const long long row = (long long)blockIdx.x * ROWS_PER_BLOCK + tid;
        const float* xr = x + row * DCOL;
        float xv[KC];
        #pragma unroll
        for (int k = 0; k < KC; ++k) xv[k] = __ldg(xr + s_xi[k]);

        float a0 = 0.f;
        #pragma unroll
        for (int k = 0; k < KC; ++k) a0 = fmaf(s_a[k], xv[k], a0);

        // quadratic form: fully unrolled triangular loop, x in registers,
        // packed-tri coefficients via broadcast LDS.128
        {
            const float4* tri4 = (const float4*)s_tri;
            float4 tb = make_float4(0.f, 0.f, 0.f, 0.f);
            int p = 0;
            #pragma unroll
            for (int i = 0; i < KC - 1; ++i) {
                float s = 0.f;
                #pragma unroll
                for (int j = i + 1; j < KC; ++j) {
                    if ((p & 3) == 0) tb = tri4[p >> 2];
                    float bv = ((p & 3) == 0) ? tb.x :
                               ((p & 3) == 1) ? tb.y :
                               ((p & 3) == 2) ? tb.z : tb.w;
                    s = fmaf(bv, xv[j], s);
                    ++p;
                }
                a0 = fmaf(s, xv[i], a0);
            }
        }
        s_acc[tid] = a0;

        // publish fp16 copy for the monomial phase (this thread's own column)
        #pragma unroll
        for (int k = 0; k < KC; ++k)
            s_x[k][tid] = __float2half(xv[k]);
    }
    __syncthreads();

    // ---------------- phase B: monomials, 2 rows at once via half2, ----------
    // ---------------- 2 threads per pair each doing half the terms ----------
    const int p  = tid & (NPAIR - 1);   // pair id 0..63
    const int h  = tid >> 6;            // term half 0/1
    // pair p covers rows (2p, 2p+1); half2 column base byte offset = 4*p
    const char* xb = (const char*)(&s_x[0][0]) + 4 * p;
    float m0 = 0.f, m1 = 0.f;

    {
        const int lo = h * (NM3 / 2), hi = lo + (NM3 / 2);
        #pragma unroll 4
        for (int t3 = lo; t3 < hi; ++t3) {
            uint2 r = s_rec3[t3];
            unsigned o0 = (r.x << 8) & 0xFF00u;
            unsigned o1 =  r.x       & 0xFF00u;
            unsigned o2 = (r.x >> 8) & 0xFF00u;
            __half2 pr = __hmul2(*(const __half2*)(xb + o0),
                                 *(const __half2*)(xb + o1));
            pr = __hmul2(pr, *(const __half2*)(xb + o2));
            float2 pf = __half22float2(pr);
            float c = __uint_as_float(r.y);
            m0 = fmaf(c, pf.x, m0);
            m1 = fmaf(c, pf.y, m1);
        }
    }
    {
        const int lo = h * (NM4 / 2), hi = lo + (NM4 / 2);
        #pragma unroll 4
        for (int t4 = lo; t4 < hi; ++t4) {
            uint2 r = s_rec4[t4];
            unsigned o0 = (r.x << 8)  & 0xFF00u;
            unsigned o1 =  r.x        & 0xFF00u;
            unsigned o2 = (r.x >> 8)  & 0xFF00u;
            unsigned o3 = (r.x >> 16) & 0xFF00u;
            __half2 p01 = __hmul2(*(const __half2*)(xb + o0),
                                  *(const __half2*)(xb + o1));
            __half2 p23 = __hmul2(*(const __half2*)(xb + o2),
                                  *(const __half2*)(xb + o3));
            __half2 pr  = __hmul2(p01, p23);
            float2 pf = __half22float2(pr);
            float c = __uint_as_float(r.y);
            m0 = fmaf(c, pf.x, m0);
            m1 = fmaf(c, pf.y, m1);
        }
    }
    {
        const int lo = h * (NM5 / 2), hi = lo + (NM5 / 2);
        #pragma unroll 4
        for (int t5 = lo; t5 < hi; ++t5) {
            uint4 r = s_rec5[t5];
            unsigned o0 = (r.x << 8)  & 0xFF00u;
            unsigned o1 =  r.x        & 0xFF00u;
            unsigned o2 = (r.x >> 8)  & 0xFF00u;
            unsigned o3 = (r.x >> 16) & 0xFF00u;
            unsigned o4 =  r.y << 8;
            __half2 p01 = __hmul2(*(const __half2*)(xb + o0),
                                  *(const __half2*)(xb + o1));
            __half2 p23 = __hmul2(*(const __half2*)(xb + o2),
                                  *(const __half2*)(xb + o3));
            __half2 pr  = __hmul2(__hmul2(p01, p23),
                                  *(const __half2*)(xb + o4));
            float2 pf = __half22float2(pr);
            float c = __uint_as_float(r.z);
            m0 = fmaf(c, pf.x, m0);
            m1 = fmaf(c, pf.y, m1);
        }
    }

    s_red[h][p] = make_float2(m0, m1);
    __syncthreads();

    if (tid < NPAIR) {
        float2 r0 = s_red[0][tid];
        float2 r1 = s_red[1][tid];
        float2 o2v;
        o2v.x = s_acc[2 * tid + 0] + r0.x + r1.x;
        o2v.y = s_acc[2 * tid + 1] + r0.y + r1.y;
        ((float2*)out)[blockIdx.x * NPAIR + tid] = o2v;
    }
}

// -------- launch --------
extern "C" void kernel_launch(void* const* d_in, const int* in_sizes, int n_in,
                              void* d_out, int out_size)
{
    const float* x    = (const float*)d_in[0];
    const int*   S    = (const int*)  d_in[1];
    const float* a    = (const float*)d_in[2];
    const float* b    = (const float*)d_in[3];
    const int*   idx3 = (const int*)  d_in[4];
    const float* c3   = (const float*)d_in[5];
    const int*   idx4 = (const int*)  d_in[6];
    const float* c4   = (const float*)d_in[7];
    const int*   idx5 = (const int*)  d_in[8];
    const float* c5   = (const float*)d_in[9];
    float* out = (float*)d_out;

    prep_kernel<<<8, 256>>>(b, S, a, idx3, c3, idx4, c4, idx5, c5);
    poly_kernel<<<NBLOCKS, TPB>>>(x, out);
}